// round 7
// baseline (speedup 1.0000x reference)
#include <cuda_runtime.h>

#define Bz 4
#define Cc 256
#define Cii 128
#define Nn 4096
#define KSsplit 16
#define KPB (Nn / KSsplit)   // 256 K per split block

typedef unsigned long long u64;

__device__ __forceinline__ u64 pack2(float lo, float hi) {
    u64 r; asm("mov.b64 %0, {%1,%2};" : "=l"(r) : "f"(lo), "f"(hi)); return r;
}
__device__ __forceinline__ float2 unpack2(u64 v) {
    float2 f; asm("mov.b64 {%0,%1}, %2;" : "=f"(f.x), "=f"(f.y) : "l"(v)); return f;
}
__device__ __forceinline__ u64 fma2(u64 a, u64 b, u64 c) {
    u64 d; asm("fma.rn.f32x2 %0, %1, %2, %3;" : "=l"(d) : "l"(a), "l"(b), "l"(c)); return d;
}

// ---------------- scratch ----------------------------------------------------
__device__ float g_R[Bz * Cc * Cc];     // R = B B^T (atomics; upper computed, lower mirrored)
__device__ float g_s[Bz * Cc];          // row sums of b image (atomics)
__device__ float g_P[Cc * Cc];          // W_w @ g_w
__device__ float g_E[Cc * Cc];          // phi_w^T @ theta_w
__device__ float g_V[Bz * Cc * Cc];     // P @ R
__device__ float g_Q[Bz * Cc * Cc];     // (V@E + rank1)/N
__device__ float g_w1[Cc];              // phi_w^T theta_b
__device__ float g_v1[Cc];              // theta_w^T phi_b
__device__ float g_u2[Cc];              // W_w g_b
__device__ float g_sc1[1];              // phi_b . theta_b
__device__ float g_u1[Bz * Cc];         // W_w gs
__device__ float g_v2[Bz * Cc];         // theta_w^T ps2
__device__ float g_dp[Bz * Cc];         // folded bias
__device__ float g_alpha[Cc];           // BN scale

// ---------------- big-tile geometry ------------------------------------------
#define PAD 132
#define TBUF (32 * PAD)
#define SMEM_BIG (4 * TBUF * 4)   // A(2 buf) + B(2 buf) = 67584 B

// ---------------- zero atomic targets -----------------------------------------
__global__ __launch_bounds__(256) void k_zero() {
    int i = blockIdx.x * 256 + threadIdx.x;
    ((float4*)g_R)[i] = make_float4(0.f, 0.f, 0.f, 0.f);
    if (i < (Bz * Cc) / 4) ((float4*)g_s)[i] = make_float4(0.f, 0.f, 0.f, 0.f);
}

// ---------------- batch-independent small vectors ------------------------------
__global__ __launch_bounds__(256) void k_pvec(
    const float* __restrict__ phiw, const float* __restrict__ thw,
    const float* __restrict__ Ww, const float* __restrict__ phib,
    const float* __restrict__ thb, const float* __restrict__ gb)
{
    int t = threadIdx.x;
    float w1 = 0.f, v1 = 0.f;
    for (int i = 0; i < Cii; i++) {
        w1 += phiw[i * Cc + t] * thb[i];
        v1 += thw[i * Cc + t] * phib[i];
    }
    g_w1[t] = w1;
    g_v1[t] = v1;
    float u2 = 0.f;
    for (int k = 0; k < Cii; k++) u2 += Ww[t * Cii + k] * gb[k];
    g_u2[t] = u2;
    if (t < 32) {
        float s = 0.f;
        for (int i = t; i < Cii; i += 32) s += phib[i] * thb[i];
        #pragma unroll
        for (int o = 16; o > 0; o >>= 1) s += __shfl_down_sync(0xffffffffu, s, o);
        if (t == 0) g_sc1[0] = s;
    }
}

// ---------------- 128x128 micro kernel ----------------------------------------
__device__ __forceinline__ void mm128(const float* __restrict__ As,
                                      const float* __restrict__ Bs,
                                      int rbase, int cbase, u64 acc[8][4]) {
    #pragma unroll 8
    for (int k = 0; k < 32; k++) {
        const float* ap = &As[k * PAD + rbase];
        const float* bp = &Bs[k * PAD + cbase];
        float4 a0 = *(const float4*)ap;
        float4 a1 = *(const float4*)(ap + 4);
        ulonglong2 b0 = *(const ulonglong2*)bp;
        ulonglong2 b1 = *(const ulonglong2*)(bp + 4);
        float av[8] = {a0.x, a0.y, a0.z, a0.w, a1.x, a1.y, a1.z, a1.w};
        #pragma unroll
        for (int i = 0; i < 8; i++) {
            u64 ad = pack2(av[i], av[i]);
            acc[i][0] = fma2(ad, b0.x, acc[i][0]);
            acc[i][1] = fma2(ad, b0.y, acc[i][1]);
            acc[i][2] = fma2(ad, b1.x, acc[i][2]);
            acc[i][3] = fma2(ad, b1.y, acc[i][3]);
        }
    }
}

// ---------------- SYRK (symmetric, split-K, atomic reduce, fused row sums) -----
// tiles: (0,0),(1,1) diagonal + (0,1) upper; mirror fills (1,0).
__global__ __launch_bounds__(256, 2) void k_syrk(const float* __restrict__ bimg) {
    extern __shared__ __align__(16) float sm[];
    float* Asm = sm;
    float* Bsm = sm + 2 * TBUF;
    const int TI[3] = {0, 1, 0};
    const int TJ[3] = {0, 1, 1};
    int ti = TI[blockIdx.x] * 128;
    int tj = TJ[blockIdx.x] * 128;
    int diag = (blockIdx.x < 2);
    int bz = blockIdx.y >> 4;
    int ks = blockIdx.y & (KSsplit - 1);
    const float* Bb = bimg + (size_t)bz * Cc * Nn;
    int tid = threadIdx.x;
    int lane = tid & 31, warp = tid >> 5;
    int r = tid & 127, kg = tid >> 7;           // scatter map: lane=row
    int rbase = warp * 16 + (lane >> 4) * 8;
    int cbase = (lane & 15) * 8;
    int k0 = ks * KPB;

    float4 va[4], vb[4];
    u64 acc[8][4] = {};
    float rs = 0.f;

    #define SY_LOAD(t) do { \
        int kb = k0 + (t) * 32; \
        _Pragma("unroll") for (int l = 0; l < 4; l++) { \
            int kk = kg * 4 + l * 8; \
            va[l] = *(const float4*)&Bb[(size_t)(ti + r) * Nn + kb + kk]; \
            vb[l] = *(const float4*)&Bb[(size_t)(tj + r) * Nn + kb + kk]; \
        } \
        if (diag) { _Pragma("unroll") for (int l = 0; l < 4; l++) \
            rs += va[l].x + va[l].y + va[l].z + va[l].w; } \
    } while (0)

    #define SY_STORE(buf) do { \
        _Pragma("unroll") for (int l = 0; l < 4; l++) { \
            int kk = kg * 4 + l * 8; \
            float ta[4]; *(float4*)ta = va[l]; \
            float tb[4]; *(float4*)tb = vb[l]; \
            _Pragma("unroll") for (int q = 0; q < 4; q++) { \
                Asm[(buf) * TBUF + (kk + q) * PAD + r] = ta[q]; \
                Bsm[(buf) * TBUF + (kk + q) * PAD + r] = tb[q]; \
            } \
        } \
    } while (0)

    const int T = KPB / 32;   // 8
    SY_LOAD(0);
    SY_STORE(0);
    SY_LOAD(1);
    __syncthreads();
    #pragma unroll 1
    for (int t = 0; t < T; t++) {
        mm128(&Asm[(t & 1) * TBUF], &Bsm[(t & 1) * TBUF], rbase, cbase, acc);
        if (t + 1 < T) SY_STORE((t + 1) & 1);
        __syncthreads();
        if (t + 2 < T) SY_LOAD(t + 2);
    }
    #undef SY_LOAD
    #undef SY_STORE

    if (diag) atomicAdd(&g_s[bz * Cc + ti + r], rs);

    float* Rb = g_R + (size_t)bz * Cc * Cc;
    #pragma unroll
    for (int i = 0; i < 8; i++) {
        int row = ti + rbase + i;
        float* dst = &Rb[(size_t)row * Cc + tj + cbase];
        #pragma unroll
        for (int j = 0; j < 4; j++) {
            float2 p = unpack2(acc[i][j]);
            atomicAdd(dst + j * 2 + 0, p.x);
            atomicAdd(dst + j * 2 + 1, p.y);
        }
    }
}

// ---------------- mirror lower-left 128x128 block of R -------------------------
__global__ __launch_bounds__(256) void k_mirror() {
    __shared__ float t[32][33];
    int cp0 = blockIdx.x * 32;          // c' in 0..127
    int c0 = 128 + blockIdx.y * 32;     // c  in 128..255
    int b = blockIdx.z;
    int tx = threadIdx.x & 31, ty = threadIdx.x >> 5;
    float* Rb = g_R + (size_t)b * Cc * Cc;
    for (int yy = ty; yy < 32; yy += 8)
        t[yy][tx] = Rb[(size_t)(cp0 + yy) * Cc + c0 + tx];
    __syncthreads();
    for (int yy = ty; yy < 32; yy += 8)
        Rb[(size_t)(c0 + yy) * Cc + cp0 + tx] = t[tx][yy];
}

// ---------------- per-batch vectors + folded bias ------------------------------
__global__ __launch_bounds__(256) void k_vec1(
    const float* __restrict__ gw, const float* __restrict__ phiw,
    const float* __restrict__ phib, const float* __restrict__ Ww,
    const float* __restrict__ thw, const float* __restrict__ thb,
    const float* __restrict__ gamma, const float* __restrict__ beta,
    const float* __restrict__ mean, const float* __restrict__ var)
{
    int b = blockIdx.x, t = threadIdx.x;
    __shared__ float ssh[Cc], gs_sm[Cii], ps2_sm[Cii], rw1_sm[Cc], sc2_sm;
    ssh[t] = g_s[b * Cc + t];
    __syncthreads();
    if (t < Cii) {
        float acc = 0.f;
        for (int c = 0; c < Cc; c++) acc += gw[t * Cc + c] * ssh[c];
        gs_sm[t] = acc;
    } else {
        int i = t - Cii;
        float acc = 0.f;
        for (int c = 0; c < Cc; c++) acc += phiw[i * Cc + c] * ssh[c];
        ps2_sm[i] = acc + (float)Nn * phib[i];
    }
    __syncthreads();
    float u1 = 0.f;
    for (int k = 0; k < Cii; k++) u1 += Ww[t * Cii + k] * gs_sm[k];
    g_u1[b * Cc + t] = u1;
    float v2 = 0.f;
    for (int i = 0; i < Cii; i++) v2 += thw[i * Cc + t] * ps2_sm[i];
    g_v2[b * Cc + t] = v2;
    float rw = 0.f;
    const float* Rrow = g_R + (size_t)b * Cc * Cc + (size_t)t * Cc;
    for (int c = 0; c < Cc; c++) rw += Rrow[c] * g_w1[c];
    rw1_sm[t] = rw;
    if (t < 32) {
        float s2 = 0.f;
        for (int i = t; i < Cii; i += 32) s2 += ps2_sm[i] * thb[i];
        #pragma unroll
        for (int o = 16; o > 0; o >>= 1) s2 += __shfl_down_sync(0xffffffffu, s2, o);
        if (t == 0) sc2_sm = s2;
    }
    __syncthreads();
    float dv = 0.f;
    for (int c = 0; c < Cc; c++) dv += g_P[t * Cc + c] * rw1_sm[c];
    dv = (dv + u1 * g_sc1[0] + g_u2[t] * sc2_sm) * (1.f / (float)Nn);
    float al = gamma[t] * rsqrtf(var[t] + 1e-5f);
    g_dp[b * Cc + t] = al * (dv - mean[t]) + beta[t];
    if (b == 0) g_alpha[t] = al;
}

// ---------------- 64x64-tile batched GEMM (chain) ------------------------------
// C[bz] = scale*(A@B [+ r1a r1b^T + r2a r2b^T]); A: [M,K] (AT=0, lda=K-ish) or
// [K,M] k-major (AT=1). B: [K,N] natural.
#define CPAD 68
#define CBUF (32 * CPAD)
__global__ __launch_bounds__(256) void k_mm64(
    const float* __restrict__ A, long long sA, int AT, int lda,
    const float* __restrict__ B, long long sB, int ldb,
    float* __restrict__ C, long long sC, int N, int K, float scale,
    const float* __restrict__ r1a, long long s1a,
    const float* __restrict__ r1b,
    const float* __restrict__ r2a,
    const float* __restrict__ r2b, long long s2b)
{
    __shared__ __align__(16) float As[2 * CBUF], Bs[2 * CBUF];
    int m0 = blockIdx.x * 64, n0 = blockIdx.y * 64, bz = blockIdx.z;
    A += (size_t)bz * sA; B += (size_t)bz * sB; C += (size_t)bz * sC;
    int tid = threadIdx.x;
    int lane = tid & 31, warp = tid >> 5;
    int rbase = warp * 8 + (lane >> 4) * 4;
    int cbase = (lane & 15) * 4;
    int ar = tid & 63, akg = tid >> 6;          // scatter map (AT=0)
    u64 acc[4][2] = {};
    float4 va[2], vb[2];

    #define CM_LOAD(t) do { \
        int kb = (t) * 32; \
        if (!AT) { \
            _Pragma("unroll") for (int l = 0; l < 2; l++) \
                va[l] = *(const float4*)&A[(size_t)(m0 + ar) * lda + kb + akg * 4 + l * 16]; \
        } else { \
            _Pragma("unroll") for (int l = 0; l < 2; l++) { \
                int e = tid + l * 256; \
                va[l] = *(const float4*)&A[(size_t)(kb + (e >> 4)) * lda + m0 + (e & 15) * 4]; \
            } \
        } \
        _Pragma("unroll") for (int l = 0; l < 2; l++) { \
            int e = tid + l * 256; \
            vb[l] = *(const float4*)&B[(size_t)(kb + (e >> 4)) * ldb + n0 + (e & 15) * 4]; \
        } \
    } while (0)

    #define CM_STORE(buf) do { \
        if (!AT) { \
            _Pragma("unroll") for (int l = 0; l < 2; l++) { \
                float tv[4]; *(float4*)tv = va[l]; \
                _Pragma("unroll") for (int q = 0; q < 4; q++) \
                    As[(buf) * CBUF + (akg * 4 + l * 16 + q) * CPAD + ar] = tv[q]; \
            } \
        } else { \
            _Pragma("unroll") for (int l = 0; l < 2; l++) { \
                int e = tid + l * 256; \
                *(float4*)&As[(buf) * CBUF + (e >> 4) * CPAD + (e & 15) * 4] = va[l]; \
            } \
        } \
        _Pragma("unroll") for (int l = 0; l < 2; l++) { \
            int e = tid + l * 256; \
            *(float4*)&Bs[(buf) * CBUF + (e >> 4) * CPAD + (e & 15) * 4] = vb[l]; \
        } \
    } while (0)

    const int T = K / 32;
    CM_LOAD(0);
    CM_STORE(0);
    if (T > 1) CM_LOAD(1);
    __syncthreads();
    #pragma unroll 1
    for (int t = 0; t < T; t++) {
        const float* Ab = &As[(t & 1) * CBUF];
        const float* Bb2 = &Bs[(t & 1) * CBUF];
        #pragma unroll 8
        for (int k = 0; k < 32; k++) {
            float4 a = *(const float4*)&Ab[k * CPAD + rbase];
            ulonglong2 bv = *(const ulonglong2*)&Bb2[k * CPAD + cbase];
            float av[4] = {a.x, a.y, a.z, a.w};
            #pragma unroll
            for (int i = 0; i < 4; i++) {
                u64 ad = pack2(av[i], av[i]);
                acc[i][0] = fma2(ad, bv.x, acc[i][0]);
                acc[i][1] = fma2(ad, bv.y, acc[i][1]);
            }
        }
        if (t + 1 < T) CM_STORE((t + 1) & 1);
        __syncthreads();
        if (t + 2 < T) CM_LOAD(t + 2);
    }
    #undef CM_LOAD
    #undef CM_STORE

    float4 w1v = make_float4(0.f, 0.f, 0.f, 0.f), w2v = w1v;
    if (r1a) {
        w1v = *(const float4*)&r1b[n0 + cbase];
        w2v = *(const float4*)&r2b[(size_t)bz * s2b + n0 + cbase];
    }
    #pragma unroll
    for (int i = 0; i < 4; i++) {
        int m = m0 + rbase + i;
        float2 p0 = unpack2(acc[i][0]), p1 = unpack2(acc[i][1]);
        float4 v = make_float4(p0.x, p0.y, p1.x, p1.y);
        if (r1a) {
            float a1 = r1a[(size_t)bz * s1a + m];
            float a2 = r2a[m];
            v.x += a1 * w1v.x + a2 * w2v.x;
            v.y += a1 * w1v.y + a2 * w2v.y;
            v.z += a1 * w1v.z + a2 * w2v.z;
            v.w += a1 * w1v.w + a2 * w2v.w;
        }
        v.x *= scale; v.y *= scale; v.z *= scale; v.w *= scale;
        *(float4*)&C[(size_t)m * N + n0 + cbase] = v;
    }
}

// ---------------- final: out[b] = alpha .* (Q[b] @ A[b]) + dp -------------------
// grid (2, 32, Bz); 128x128 tiles; Q scatter-loaded, A natural.
__global__ __launch_bounds__(256, 2) void k_out(const float* __restrict__ aimg,
                                                float* __restrict__ out)
{
    extern __shared__ __align__(16) float sm[];
    float* Qs = sm;
    float* Bs = sm + 2 * TBUF;
    int tc = blockIdx.x * 128;
    int tn = blockIdx.y * 128;
    int bz = blockIdx.z;
    const float* Ab = aimg + (size_t)bz * Cc * Nn;
    const float* Qb = g_Q + (size_t)bz * Cc * Cc;
    int tid = threadIdx.x;
    int lane = tid & 31, warp = tid >> 5;
    int r = tid & 127, kg = tid >> 7;
    int rbase = warp * 16 + (lane >> 4) * 8;
    int cbase = (lane & 15) * 8;

    float4 vq[4], vb[4];
    u64 acc[8][4] = {};

    #define FO_LOAD(t) do { \
        int kb = (t) * 32; \
        _Pragma("unroll") for (int l = 0; l < 4; l++) \
            vq[l] = *(const float4*)&Qb[(size_t)(tc + r) * Cc + kb + kg * 4 + l * 8]; \
        _Pragma("unroll") for (int l = 0; l < 4; l++) { \
            int e = tid + l * 256; \
            vb[l] = *(const float4*)&Ab[(size_t)(kb + (e >> 5)) * Nn + tn + (e & 31) * 4]; \
        } \
    } while (0)

    #define FO_STORE(buf) do { \
        _Pragma("unroll") for (int l = 0; l < 4; l++) { \
            float tv[4]; *(float4*)tv = vq[l]; \
            _Pragma("unroll") for (int q = 0; q < 4; q++) \
                Qs[(buf) * TBUF + (kg * 4 + l * 8 + q) * PAD + r] = tv[q]; \
        } \
        _Pragma("unroll") for (int l = 0; l < 4; l++) { \
            int e = tid + l * 256; \
            *(float4*)&Bs[(buf) * TBUF + (e >> 5) * PAD + (e & 31) * 4] = vb[l]; \
        } \
    } while (0)

    const int T = Cc / 32;   // 8
    FO_LOAD(0);
    FO_STORE(0);
    FO_LOAD(1);
    __syncthreads();
    #pragma unroll 1
    for (int t = 0; t < T; t++) {
        mm128(&Qs[(t & 1) * TBUF], &Bs[(t & 1) * TBUF], rbase, cbase, acc);
        if (t + 1 < T) FO_STORE((t + 1) & 1);
        __syncthreads();
        if (t + 2 < T) FO_LOAD(t + 2);
    }
    #undef FO_LOAD
    #undef FO_STORE

    float* outb = out + (size_t)bz * Cc * Nn;
    #pragma unroll
    for (int i = 0; i < 8; i++) {
        int c = tc + rbase + i;
        float al = g_alpha[c];
        float dpv = g_dp[bz * Cc + c];
        float2 p0 = unpack2(acc[i][0]), p1 = unpack2(acc[i][1]);
        float2 p2 = unpack2(acc[i][2]), p3 = unpack2(acc[i][3]);
        float* dst = &outb[(size_t)c * Nn + tn + cbase];
        *(float4*)dst = make_float4(al * p0.x + dpv, al * p0.y + dpv,
                                    al * p1.x + dpv, al * p1.y + dpv);
        *(float4*)(dst + 4) = make_float4(al * p2.x + dpv, al * p2.y + dpv,
                                          al * p3.x + dpv, al * p3.y + dpv);
    }
}

// -------------------------------------------------------------------------------
extern "C" void kernel_launch(void* const* d_in, const int* in_sizes, int n_in,
                              void* d_out, int out_size) {
    (void)in_sizes; (void)n_in; (void)out_size;
    const float* a       = (const float*)d_in[0];
    const float* bimg    = (const float*)d_in[1];
    const float* theta_w = (const float*)d_in[2];
    const float* theta_b = (const float*)d_in[3];
    const float* phi_w   = (const float*)d_in[4];
    const float* phi_b   = (const float*)d_in[5];
    const float* g_wp    = (const float*)d_in[6];
    const float* g_bp    = (const float*)d_in[7];
    const float* W_wp    = (const float*)d_in[8];
    const float* gamma   = (const float*)d_in[9];
    const float* beta    = (const float*)d_in[10];
    const float* mean    = (const float*)d_in[11];
    const float* var     = (const float*)d_in[12];

    static int attr_done = 0;
    if (!attr_done) {
        cudaFuncSetAttribute(k_syrk, cudaFuncAttributeMaxDynamicSharedMemorySize, SMEM_BIG);
        cudaFuncSetAttribute(k_out,  cudaFuncAttributeMaxDynamicSharedMemorySize, SMEM_BIG);
        attr_done = 1;
    }

    float *pR, *pP, *pE, *pV, *pQ, *pU1, *pV1, *pU2, *pV2;
    cudaGetSymbolAddress((void**)&pR,  g_R);
    cudaGetSymbolAddress((void**)&pP,  g_P);
    cudaGetSymbolAddress((void**)&pE,  g_E);
    cudaGetSymbolAddress((void**)&pV,  g_V);
    cudaGetSymbolAddress((void**)&pQ,  g_Q);
    cudaGetSymbolAddress((void**)&pU1, g_u1);
    cudaGetSymbolAddress((void**)&pV1, g_v1);
    cudaGetSymbolAddress((void**)&pU2, g_u2);
    cudaGetSymbolAddress((void**)&pV2, g_v2);

    k_zero<<<(Bz * Cc * Cc / 4) / 256, 256>>>();
    k_pvec<<<1, 256>>>(phi_w, theta_w, W_wp, phi_b, theta_b, g_bp);

    // P = W_w @ g_w   [256,256], K=128
    k_mm64<<<dim3(4, 4, 1), 256>>>(W_wp, 0, 0, Cii, g_wp, 0, Cc, pP, 0, Cc, Cii, 1.f,
                                   nullptr, 0, nullptr, nullptr, nullptr, 0);
    // E = phi_w^T @ theta_w  (AT: phi_w stored [K=128, M=256])
    k_mm64<<<dim3(4, 4, 1), 256>>>(phi_w, 0, 1, Cc, theta_w, 0, Cc, pE, 0, Cc, Cii, 1.f,
                                   nullptr, 0, nullptr, nullptr, nullptr, 0);

    k_syrk<<<dim3(3, Bz * KSsplit), 256, SMEM_BIG>>>(bimg);
    k_mirror<<<dim3(4, 4, Bz), 256>>>();
    k_vec1<<<Bz, 256>>>(g_wp, phi_w, phi_b, W_wp, theta_w, theta_b,
                        gamma, beta, mean, var);

    // V[b] = P @ R[b]   K=256
    k_mm64<<<dim3(4, 4, Bz), 256>>>(pP, 0, 0, Cc, pR, (long long)Cc * Cc, Cc,
                                    pV, (long long)Cc * Cc, Cc, Cc, 1.f,
                                    nullptr, 0, nullptr, nullptr, nullptr, 0);
    // Q[b] = (V[b] @ E + u1 v1^T + u2 v2^T) / N
    k_mm64<<<dim3(4, 4, Bz), 256>>>(pV, (long long)Cc * Cc, 0, Cc, pE, 0, Cc,
                                    pQ, (long long)Cc * Cc, Cc, Cc, 1.f / (float)Nn,
                                    pU1, Cc, pV1, pU2, pV2, Cc);

    k_out<<<dim3(2, 32, Bz), 256, SMEM_BIG>>>(a, (float*)d_out);
}

// round 8
// speedup vs baseline: 1.1119x; 1.1119x over previous
#include <cuda_runtime.h>

#define Bz 4
#define Cc 256
#define Cii 128
#define Nn 4096
#define KSsplit 16
#define KPB (Nn / KSsplit)   // 256 K per split block

typedef unsigned long long u64;

__device__ __forceinline__ u64 pack2(float lo, float hi) {
    u64 r; asm("mov.b64 %0, {%1,%2};" : "=l"(r) : "f"(lo), "f"(hi)); return r;
}
__device__ __forceinline__ float2 unpack2(u64 v) {
    float2 f; asm("mov.b64 {%0,%1}, %2;" : "=f"(f.x), "=f"(f.y) : "l"(v)); return f;
}
__device__ __forceinline__ u64 fma2(u64 a, u64 b, u64 c) {
    u64 d; asm("fma.rn.f32x2 %0, %1, %2, %3;" : "=l"(d) : "l"(a), "l"(b), "l"(c)); return d;
}

// ---------------- scratch ----------------------------------------------------
__device__ float g_R[Bz * Cc * Cc];     // R = B B^T (atomics; lower-left mirrored)
__device__ float g_s[Bz * Cc];          // row sums of b image (atomics)
__device__ float g_P[Cc * Cc];          // W_w @ g_w
__device__ float g_E[Cc * Cc];          // phi_w^T @ theta_w
__device__ float g_V[Bz * Cc * Cc];     // P @ R
__device__ float g_Q[Bz * Cc * Cc];     // (V@E + rank1)/N
__device__ float g_w1[Cc];              // phi_w^T theta_b
__device__ float g_v1[Cc];              // theta_w^T phi_b
__device__ float g_u2[Cc];              // W_w g_b
__device__ float g_sc1[1];              // phi_b . theta_b
__device__ float g_u1[Bz * Cc];         // W_w gs
__device__ float g_v2[Bz * Cc];         // theta_w^T ps2
__device__ float g_dp[Bz * Cc];         // folded bias
__device__ float g_alpha[Cc];           // BN scale

// smem tile geometry (R4 proven: transposed k-major tiles)
#define APAD 68
#define BPAD 132
#define ABUF (32 * APAD)
#define BBUF (32 * BPAD)
#define SMEM_BYTES ((2 * ABUF + 2 * BBUF) * 4)   // 51200

// ---------------- zero atomic targets -----------------------------------------
__global__ __launch_bounds__(256) void k_zero() {
    int i = blockIdx.x * 256 + threadIdx.x;
    ((float4*)g_R)[i] = make_float4(0.f, 0.f, 0.f, 0.f);
    if (i < (Bz * Cc) / 4) ((float4*)g_s)[i] = make_float4(0.f, 0.f, 0.f, 0.f);
}

// ---------------- batch-independent small vectors ------------------------------
__global__ __launch_bounds__(256) void k_pvec(
    const float* __restrict__ phiw, const float* __restrict__ thw,
    const float* __restrict__ Ww, const float* __restrict__ phib,
    const float* __restrict__ thb, const float* __restrict__ gb)
{
    int t = threadIdx.x;
    float w1 = 0.f, v1 = 0.f;
    for (int i = 0; i < Cii; i++) {
        w1 += phiw[i * Cc + t] * thb[i];
        v1 += thw[i * Cc + t] * phib[i];
    }
    g_w1[t] = w1;
    g_v1[t] = v1;
    float u2 = 0.f;
    for (int k = 0; k < Cii; k++) u2 += Ww[t * Cii + k] * gb[k];
    g_u2[t] = u2;
    if (t < 32) {
        float s = 0.f;
        for (int i = t; i < Cii; i += 32) s += phib[i] * thb[i];
        #pragma unroll
        for (int o = 16; o > 0; o >>= 1) s += __shfl_down_sync(0xffffffffu, s, o);
        if (t == 0) g_sc1[0] = s;
    }
}

// ---------------- shared inner product micro-kernel (R4) -----------------------
__device__ __forceinline__ void mm_compute(const float* __restrict__ Asm,
                                           const float* __restrict__ Bsn,
                                           int warp, int lane, u64 acc[8][2]) {
    #pragma unroll 8
    for (int k = 0; k < 32; k++) {
        ulonglong2 bv = *(const ulonglong2*)&Bsn[k * BPAD + lane * 4];
        float4 a0 = *(const float4*)&Asm[k * APAD + warp * 8];
        float4 a1 = *(const float4*)&Asm[k * APAD + warp * 8 + 4];
        u64 ad;
        ad = pack2(a0.x, a0.x); acc[0][0] = fma2(ad, bv.x, acc[0][0]); acc[0][1] = fma2(ad, bv.y, acc[0][1]);
        ad = pack2(a0.y, a0.y); acc[1][0] = fma2(ad, bv.x, acc[1][0]); acc[1][1] = fma2(ad, bv.y, acc[1][1]);
        ad = pack2(a0.z, a0.z); acc[2][0] = fma2(ad, bv.x, acc[2][0]); acc[2][1] = fma2(ad, bv.y, acc[2][1]);
        ad = pack2(a0.w, a0.w); acc[3][0] = fma2(ad, bv.x, acc[3][0]); acc[3][1] = fma2(ad, bv.y, acc[3][1]);
        ad = pack2(a1.x, a1.x); acc[4][0] = fma2(ad, bv.x, acc[4][0]); acc[4][1] = fma2(ad, bv.y, acc[4][1]);
        ad = pack2(a1.y, a1.y); acc[5][0] = fma2(ad, bv.x, acc[5][0]); acc[5][1] = fma2(ad, bv.y, acc[5][1]);
        ad = pack2(a1.z, a1.z); acc[6][0] = fma2(ad, bv.x, acc[6][0]); acc[6][1] = fma2(ad, bv.y, acc[6][1]);
        ad = pack2(a1.w, a1.w); acc[7][0] = fma2(ad, bv.x, acc[7][0]); acc[7][1] = fma2(ad, bv.y, acc[7][1]);
    }
}

// ---------------- symmetric split-K SYRK (R4 layout, 6 of 8 tiles) -------------
// Tiles (i:64-row, j:128-col): (0,0),(1,0),(0,1),(1,1),(2,1),(3,1).
// Missing lower-left (2,0),(3,0) filled by k_mirror. Row sums fused: counted
// once by blocks with x<2 (j=0 rows 0..127) and x>3 (j=1 rows 128..255).
__global__ __launch_bounds__(256) void k_syrk(const float* __restrict__ bimg) {
    extern __shared__ __align__(16) float sm[];
    float* Asm = sm;
    float* Bsn = sm + 2 * ABUF;
    const int TI[6] = {0, 1, 0, 1, 2, 3};
    const int TJ[6] = {0, 0, 1, 1, 1, 1};
    int ti = TI[blockIdx.x] * 64;
    int tj = TJ[blockIdx.x] * 128;
    int do_rs = (blockIdx.x < 2) || (blockIdx.x > 3);
    int bz = blockIdx.y >> 4;
    int ks = blockIdx.y & (KSsplit - 1);
    const float* Bb = bimg + (size_t)bz * Cc * Nn;
    int tid = threadIdx.x;
    int lane = tid & 31, warp = tid >> 5;
    int k0 = ks * KPB;

    float4 va[2], vb[4];
    u64 acc[8][2] = {};
    float rs0 = 0.f, rs1 = 0.f;

    int ar[2], ak[2], br[4], bk[4];
    #pragma unroll
    for (int l = 0; l < 2; l++) { int e = tid + l * 256; ar[l] = e >> 3; ak[l] = (e & 7) * 4; }
    #pragma unroll
    for (int l = 0; l < 4; l++) { int e = tid + l * 256; br[l] = e >> 3; bk[l] = (e & 7) * 4; }

    #define SY_LOAD(t) do { \
        int kb = k0 + (t) * 32; \
        _Pragma("unroll") for (int l = 0; l < 2; l++) \
            va[l] = *(const float4*)&Bb[(size_t)(ti + ar[l]) * Nn + kb + ak[l]]; \
        _Pragma("unroll") for (int l = 0; l < 4; l++) \
            vb[l] = *(const float4*)&Bb[(size_t)(tj + br[l]) * Nn + kb + bk[l]]; \
    } while (0)

    #define SY_STORE(buf) do { \
        _Pragma("unroll") for (int l = 0; l < 2; l++) { \
            float tv[4]; *(float4*)tv = va[l]; \
            _Pragma("unroll") for (int q = 0; q < 4; q++) \
                Asm[(buf) * ABUF + (ak[l] + q) * APAD + ar[l]] = tv[q]; \
        } \
        rs0 += va[0].x + va[0].y + va[0].z + va[0].w; \
        rs1 += va[1].x + va[1].y + va[1].z + va[1].w; \
        _Pragma("unroll") for (int l = 0; l < 4; l++) { \
            float tv[4]; *(float4*)tv = vb[l]; \
            _Pragma("unroll") for (int q = 0; q < 4; q++) \
                Bsn[(buf) * BBUF + (bk[l] + q) * BPAD + br[l]] = tv[q]; \
        } \
    } while (0)

    const int T = KPB / 32;   // 8
    SY_LOAD(0);
    SY_STORE(0);
    SY_LOAD(1);
    __syncthreads();
    #pragma unroll 1
    for (int t = 0; t < T; t++) {
        mm_compute(&Asm[(t & 1) * ABUF], &Bsn[(t & 1) * BBUF], warp, lane, acc);
        if (t + 1 < T) SY_STORE((t + 1) & 1);
        __syncthreads();
        if (t + 2 < T) SY_LOAD(t + 2);
    }
    #undef SY_LOAD
    #undef SY_STORE

    if (do_rs) {
        atomicAdd(&g_s[bz * Cc + ti + ar[0]], rs0);
        atomicAdd(&g_s[bz * Cc + ti + ar[1]], rs1);
    }

    float* Rb = g_R + (size_t)bz * Cc * Cc;
    #pragma unroll
    for (int i = 0; i < 8; i++) {
        int ci = ti + warp * 8 + i;
        float2 p0 = unpack2(acc[i][0]), p1 = unpack2(acc[i][1]);
        float* dst = &Rb[(size_t)ci * Cc + tj + lane * 4];
        atomicAdd(dst + 0, p0.x);
        atomicAdd(dst + 1, p0.y);
        atomicAdd(dst + 2, p1.x);
        atomicAdd(dst + 3, p1.y);
    }
}

// ---------------- mirror lower-left 128x128 block of R -------------------------
__global__ __launch_bounds__(256) void k_mirror() {
    __shared__ float t[32][33];
    int cp0 = blockIdx.x * 32;          // c' in 0..127
    int c0 = 128 + blockIdx.y * 32;     // c  in 128..255
    int b = blockIdx.z;
    int tx = threadIdx.x & 31, ty = threadIdx.x >> 5;
    float* Rb = g_R + (size_t)b * Cc * Cc;
    for (int yy = ty; yy < 32; yy += 8)
        t[yy][tx] = Rb[(size_t)(cp0 + yy) * Cc + c0 + tx];
    __syncthreads();
    for (int yy = ty; yy < 32; yy += 8)
        Rb[(size_t)(c0 + yy) * Cc + cp0 + tx] = t[tx][yy];
}

// ---------------- per-batch vectors + folded bias ------------------------------
__global__ __launch_bounds__(256) void k_vec1(
    const float* __restrict__ gw, const float* __restrict__ phiw,
    const float* __restrict__ phib, const float* __restrict__ Ww,
    const float* __restrict__ thw, const float* __restrict__ thb,
    const float* __restrict__ gamma, const float* __restrict__ beta,
    const float* __restrict__ mean, const float* __restrict__ var)
{
    int b = blockIdx.x, t = threadIdx.x;
    __shared__ float ssh[Cc], gs_sm[Cii], ps2_sm[Cii], rw1_sm[Cc], sc2_sm;
    ssh[t] = g_s[b * Cc + t];
    __syncthreads();
    if (t < Cii) {
        float acc = 0.f;
        for (int c = 0; c < Cc; c++) acc += gw[t * Cc + c] * ssh[c];
        gs_sm[t] = acc;
    } else {
        int i = t - Cii;
        float acc = 0.f;
        for (int c = 0; c < Cc; c++) acc += phiw[i * Cc + c] * ssh[c];
        ps2_sm[i] = acc + (float)Nn * phib[i];
    }
    __syncthreads();
    float u1 = 0.f;
    for (int k = 0; k < Cii; k++) u1 += Ww[t * Cii + k] * gs_sm[k];
    g_u1[b * Cc + t] = u1;
    float v2 = 0.f;
    for (int i = 0; i < Cii; i++) v2 += thw[i * Cc + t] * ps2_sm[i];
    g_v2[b * Cc + t] = v2;
    float rw = 0.f;
    const float* Rrow = g_R + (size_t)b * Cc * Cc + (size_t)t * Cc;
    for (int c = 0; c < Cc; c++) rw += Rrow[c] * g_w1[c];
    rw1_sm[t] = rw;
    if (t < 32) {
        float s2 = 0.f;
        for (int i = t; i < Cii; i += 32) s2 += ps2_sm[i] * thb[i];
        #pragma unroll
        for (int o = 16; o > 0; o >>= 1) s2 += __shfl_down_sync(0xffffffffu, s2, o);
        if (t == 0) sc2_sm = s2;
    }
    __syncthreads();
    float dv = 0.f;
    for (int c = 0; c < Cc; c++) dv += g_P[t * Cc + c] * rw1_sm[c];
    dv = (dv + u1 * g_sc1[0] + g_u2[t] * sc2_sm) * (1.f / (float)Nn);
    float al = gamma[t] * rsqrtf(var[t] + 1e-5f);
    g_dp[b * Cc + t] = al * (dv - mean[t]) + beta[t];
    if (b == 0) g_alpha[t] = al;
}

// ---------------- 64x64-tile batched GEMM (chain) ------------------------------
#define CPAD 68
#define CBUF (32 * CPAD)
__global__ __launch_bounds__(256) void k_mm64(
    const float* __restrict__ A, long long sA, int AT, int lda,
    const float* __restrict__ B, long long sB, int ldb,
    float* __restrict__ C, long long sC, int N, int K, float scale,
    const float* __restrict__ r1a, long long s1a,
    const float* __restrict__ r1b,
    const float* __restrict__ r2a,
    const float* __restrict__ r2b, long long s2b)
{
    __shared__ __align__(16) float As[2 * CBUF], Bs[2 * CBUF];
    int m0 = blockIdx.x * 64, n0 = blockIdx.y * 64, bz = blockIdx.z;
    A += (size_t)bz * sA; B += (size_t)bz * sB; C += (size_t)bz * sC;
    int tid = threadIdx.x;
    int lane = tid & 31, warp = tid >> 5;
    int rbase = warp * 8 + (lane >> 4) * 4;
    int cbase = (lane & 15) * 4;
    int ar = tid & 63, akg = tid >> 6;
    u64 acc[4][2] = {};
    float4 va[2], vb[2];

    #define CM_LOAD(t) do { \
        int kb = (t) * 32; \
        if (!AT) { \
            _Pragma("unroll") for (int l = 0; l < 2; l++) \
                va[l] = *(const float4*)&A[(size_t)(m0 + ar) * lda + kb + akg * 4 + l * 16]; \
        } else { \
            _Pragma("unroll") for (int l = 0; l < 2; l++) { \
                int e = tid + l * 256; \
                va[l] = *(const float4*)&A[(size_t)(kb + (e >> 4)) * lda + m0 + (e & 15) * 4]; \
            } \
        } \
        _Pragma("unroll") for (int l = 0; l < 2; l++) { \
            int e = tid + l * 256; \
            vb[l] = *(const float4*)&B[(size_t)(kb + (e >> 4)) * ldb + n0 + (e & 15) * 4]; \
        } \
    } while (0)

    #define CM_STORE(buf) do { \
        if (!AT) { \
            _Pragma("unroll") for (int l = 0; l < 2; l++) { \
                float tv[4]; *(float4*)tv = va[l]; \
                _Pragma("unroll") for (int q = 0; q < 4; q++) \
                    As[(buf) * CBUF + (akg * 4 + l * 16 + q) * CPAD + ar] = tv[q]; \
            } \
        } else { \
            _Pragma("unroll") for (int l = 0; l < 2; l++) { \
                int e = tid + l * 256; \
                *(float4*)&As[(buf) * CBUF + (e >> 4) * CPAD + (e & 15) * 4] = va[l]; \
            } \
        } \
        _Pragma("unroll") for (int l = 0; l < 2; l++) { \
            int e = tid + l * 256; \
            *(float4*)&Bs[(buf) * CBUF + (e >> 4) * CPAD + (e & 15) * 4] = vb[l]; \
        } \
    } while (0)

    const int T = K / 32;
    CM_LOAD(0);
    CM_STORE(0);
    if (T > 1) CM_LOAD(1);
    __syncthreads();
    #pragma unroll 1
    for (int t = 0; t < T; t++) {
        const float* Ab = &As[(t & 1) * CBUF];
        const float* Bb2 = &Bs[(t & 1) * CBUF];
        #pragma unroll 8
        for (int k = 0; k < 32; k++) {
            float4 a = *(const float4*)&Ab[k * CPAD + rbase];
            ulonglong2 bv = *(const ulonglong2*)&Bb2[k * CPAD + cbase];
            float av[4] = {a.x, a.y, a.z, a.w};
            #pragma unroll
            for (int i = 0; i < 4; i++) {
                u64 ad = pack2(av[i], av[i]);
                acc[i][0] = fma2(ad, bv.x, acc[i][0]);
                acc[i][1] = fma2(ad, bv.y, acc[i][1]);
            }
        }
        if (t + 1 < T) CM_STORE((t + 1) & 1);
        __syncthreads();
        if (t + 2 < T) CM_LOAD(t + 2);
    }
    #undef CM_LOAD
    #undef CM_STORE

    float4 w1v = make_float4(0.f, 0.f, 0.f, 0.f), w2v = w1v;
    if (r1a) {
        w1v = *(const float4*)&r1b[n0 + cbase];
        w2v = *(const float4*)&r2b[(size_t)bz * s2b + n0 + cbase];
    }
    #pragma unroll
    for (int i = 0; i < 4; i++) {
        int m = m0 + rbase + i;
        float2 p0 = unpack2(acc[i][0]), p1 = unpack2(acc[i][1]);
        float4 v = make_float4(p0.x, p0.y, p1.x, p1.y);
        if (r1a) {
            float a1 = r1a[(size_t)bz * s1a + m];
            float a2 = r2a[m];
            v.x += a1 * w1v.x + a2 * w2v.x;
            v.y += a1 * w1v.y + a2 * w2v.y;
            v.z += a1 * w1v.z + a2 * w2v.z;
            v.w += a1 * w1v.w + a2 * w2v.w;
        }
        v.x *= scale; v.y *= scale; v.z *= scale; v.w *= scale;
        *(float4*)&C[(size_t)m * N + n0 + cbase] = v;
    }
}

// ---------------- final: out[b] = alpha .* (Q[b] @ A[b]) + dp  (R4 proven) ------
__global__ __launch_bounds__(256) void k_out(const float* __restrict__ aimg,
                                             float* __restrict__ out)
{
    extern __shared__ __align__(16) float sm[];
    float* Qs  = sm;
    float* Asn = sm + 2 * ABUF;
    int tc = blockIdx.x * 64;
    int tn = blockIdx.y * 128;
    int bz = blockIdx.z;
    const float* Ab = aimg + (size_t)bz * Cc * Nn;
    const float* Qb = g_Q + (size_t)bz * Cc * Cc;
    int tid = threadIdx.x;
    int lane = tid & 31, warp = tid >> 5;

    float4 vq[2], va[4];
    u64 acc[8][2] = {};

    int qr[2], qk[2], akr[4], anq[4];
    #pragma unroll
    for (int l = 0; l < 2; l++) { int e = tid + l * 256; qr[l] = e >> 3; qk[l] = (e & 7) * 4; }
    #pragma unroll
    for (int l = 0; l < 4; l++) { int e = tid + l * 256; akr[l] = e >> 5; anq[l] = (e & 31) * 4; }

    #define FO_LOAD(t) do { \
        int kb = (t) * 32; \
        _Pragma("unroll") for (int l = 0; l < 2; l++) \
            vq[l] = *(const float4*)&Qb[(size_t)(tc + qr[l]) * Cc + kb + qk[l]]; \
        _Pragma("unroll") for (int l = 0; l < 4; l++) \
            va[l] = *(const float4*)&Ab[(size_t)(kb + akr[l]) * Nn + tn + anq[l]]; \
    } while (0)

    #define FO_STORE(buf) do { \
        _Pragma("unroll") for (int l = 0; l < 2; l++) { \
            float tv[4]; *(float4*)tv = vq[l]; \
            _Pragma("unroll") for (int q = 0; q < 4; q++) \
                Qs[(buf) * ABUF + (qk[l] + q) * APAD + qr[l]] = tv[q]; \
        } \
        _Pragma("unroll") for (int l = 0; l < 4; l++) \
            *(float4*)&Asn[(buf) * BBUF + akr[l] * BPAD + anq[l]] = va[l]; \
    } while (0)

    const int T = Cc / 32;   // 8
    FO_LOAD(0);
    FO_STORE(0);
    FO_LOAD(1);
    __syncthreads();
    #pragma unroll 1
    for (int t = 0; t < T; t++) {
        mm_compute(&Qs[(t & 1) * ABUF], &Asn[(t & 1) * BBUF], warp, lane, acc);
        if (t + 1 < T) FO_STORE((t + 1) & 1);
        __syncthreads();
        if (t + 2 < T) FO_LOAD(t + 2);
    }
    #undef FO_LOAD
    #undef FO_STORE

    float* outb = out + (size_t)bz * Cc * Nn;
    #pragma unroll
    for (int i = 0; i < 8; i++) {
        int c = tc + warp * 8 + i;
        float al = g_alpha[c];
        float dpv = g_dp[bz * Cc + c];
        float2 p0 = unpack2(acc[i][0]), p1 = unpack2(acc[i][1]);
        *(float4*)&outb[(size_t)c * Nn + tn + lane * 4] =
            make_float4(al * p0.x + dpv, al * p0.y + dpv, al * p1.x + dpv, al * p1.y + dpv);
    }
}

// -------------------------------------------------------------------------------
extern "C" void kernel_launch(void* const* d_in, const int* in_sizes, int n_in,
                              void* d_out, int out_size) {
    (void)in_sizes; (void)n_in; (void)out_size;
    const float* a       = (const float*)d_in[0];
    const float* bimg    = (const float*)d_in[1];
    const float* theta_w = (const float*)d_in[2];
    const float* theta_b = (const float*)d_in[3];
    const float* phi_w   = (const float*)d_in[4];
    const float* phi_b   = (const float*)d_in[5];
    const float* g_wp    = (const float*)d_in[6];
    const float* g_bp    = (const float*)d_in[7];
    const float* W_wp    = (const float*)d_in[8];
    const float* gamma   = (const float*)d_in[9];
    const float* beta    = (const float*)d_in[10];
    const float* mean    = (const float*)d_in[11];
    const float* var     = (const float*)d_in[12];

    static int attr_done = 0;
    if (!attr_done) {
        cudaFuncSetAttribute(k_syrk, cudaFuncAttributeMaxDynamicSharedMemorySize, SMEM_BYTES);
        cudaFuncSetAttribute(k_out,  cudaFuncAttributeMaxDynamicSharedMemorySize, SMEM_BYTES);
        attr_done = 1;
    }

    float *pR, *pP, *pE, *pV, *pQ, *pU1, *pV1, *pU2, *pV2;
    cudaGetSymbolAddress((void**)&pR,  g_R);
    cudaGetSymbolAddress((void**)&pP,  g_P);
    cudaGetSymbolAddress((void**)&pE,  g_E);
    cudaGetSymbolAddress((void**)&pV,  g_V);
    cudaGetSymbolAddress((void**)&pQ,  g_Q);
    cudaGetSymbolAddress((void**)&pU1, g_u1);
    cudaGetSymbolAddress((void**)&pV1, g_v1);
    cudaGetSymbolAddress((void**)&pU2, g_u2);
    cudaGetSymbolAddress((void**)&pV2, g_v2);

    k_zero<<<(Bz * Cc * Cc / 4) / 256, 256>>>();
    k_pvec<<<1, 256>>>(phi_w, theta_w, W_wp, phi_b, theta_b, g_bp);

    // P = W_w @ g_w   [256,256], K=128
    k_mm64<<<dim3(4, 4, 1), 256>>>(W_wp, 0, 0, Cii, g_wp, 0, Cc, pP, 0, Cc, Cii, 1.f,
                                   nullptr, 0, nullptr, nullptr, nullptr, 0);
    // E = phi_w^T @ theta_w   [256,256], K=128 (phi_w stored [128,256] k-major)
    k_mm64<<<dim3(4, 4, 1), 256>>>(phi_w, 0, 1, Cc, theta_w, 0, Cc, pE, 0, Cc, Cii, 1.f,
                                   nullptr, 0, nullptr, nullptr, nullptr, 0);

    // symmetric SYRK (6 of 8 tiles) + mirror
    k_syrk<<<dim3(6, Bz * KSsplit), 256, SMEM_BYTES>>>(bimg);
    k_mirror<<<dim3(4, 4, Bz), 256>>>();
    k_vec1<<<Bz, 256>>>(g_wp, phi_w, phi_b, W_wp, theta_w, theta_b,
                        gamma, beta, mean, var);

    // V[b] = P @ R[b]   K=256
    k_mm64<<<dim3(4, 4, Bz), 256>>>(pP, 0, 0, Cc, pR, (long long)Cc * Cc, Cc,
                                    pV, (long long)Cc * Cc, Cc, Cc, 1.f,
                                    nullptr, 0, nullptr, nullptr, nullptr, 0);
    // Q[b] = (V[b] @ E + u1 v1^T + u2 v2^T) / N
    k_mm64<<<dim3(4, 4, Bz), 256>>>(pV, (long long)Cc * Cc, 0, Cc, pE, 0, Cc,
                                    pQ, (long long)Cc * Cc, Cc, Cc, 1.f / (float)Nn,
                                    pU1, Cc, pV1, pU2, pV2, Cc);

    k_out<<<dim3(4, 32, Bz), 256, SMEM_BYTES>>>(a, (float*)d_out);
}

// round 9
// speedup vs baseline: 1.3685x; 1.2308x over previous
#include <cuda_runtime.h>

#define Bz 4
#define Cc 256
#define Cii 128
#define Nn 4096
#define KSsplit 16
#define KPB (Nn / KSsplit)   // 256 K per split block

typedef unsigned long long u64;

__device__ __forceinline__ u64 pack2(float lo, float hi) {
    u64 r; asm("mov.b64 %0, {%1,%2};" : "=l"(r) : "f"(lo), "f"(hi)); return r;
}
__device__ __forceinline__ float2 unpack2(u64 v) {
    float2 f; asm("mov.b64 {%0,%1}, %2;" : "=f"(f.x), "=f"(f.y) : "l"(v)); return f;
}
__device__ __forceinline__ u64 fma2(u64 a, u64 b, u64 c) {
    u64 d; asm("fma.rn.f32x2 %0, %1, %2, %3;" : "=l"(d) : "l"(a), "l"(b), "l"(c)); return d;
}

// ---------------- scratch ----------------------------------------------------
__device__ float g_R[Bz * Cc * Cc];     // R = B B^T (atomics)
__device__ float g_s[Bz * Cc];          // row sums of b image (atomics)
__device__ float g_P[Cc * Cc];          // W_w @ g_w
__device__ float g_E[Cc * Cc];          // phi_w^T @ theta_w
__device__ float g_V[Bz * Cc * Cc];     // P @ R
__device__ float g_Q[Bz * Cc * Cc];     // (V@E + rank1)/N
__device__ float g_w1[Cc];              // phi_w^T theta_b
__device__ float g_v1[Cc];              // theta_w^T phi_b
__device__ float g_u2[Cc];              // W_w g_b
__device__ float g_sc1[1];              // phi_b . theta_b
__device__ float g_sc2[Bz];             // ps2 . theta_b
__device__ float g_u1[Bz * Cc];         // W_w gs
__device__ float g_v2[Bz * Cc];         // theta_w^T ps2
__device__ float g_dp[Bz * Cc];         // folded bias
__device__ float g_alpha[Cc];           // BN scale

// smem tile geometry (R4 proven)
#define APAD 68
#define BPAD 132
#define ABUF (32 * APAD)
#define BBUF (32 * BPAD)
#define SMEM_BYTES ((2 * ABUF + 2 * BBUF) * 4)   // 51200

// ---------------- zero atomic targets -----------------------------------------
__global__ __launch_bounds__(256) void k_zero() {
    int i = blockIdx.x * 256 + threadIdx.x;
    ((float4*)g_R)[i] = make_float4(0.f, 0.f, 0.f, 0.f);
    if (i < (Bz * Cc) / 4) ((float4*)g_s)[i] = make_float4(0.f, 0.f, 0.f, 0.f);
}

// ---------------- batch-independent small vectors (side stream) ----------------
__global__ __launch_bounds__(256) void k_pvec(
    const float* __restrict__ phiw, const float* __restrict__ thw,
    const float* __restrict__ Ww, const float* __restrict__ phib,
    const float* __restrict__ thb, const float* __restrict__ gb)
{
    int t = threadIdx.x;
    float w1 = 0.f, v1 = 0.f;
    for (int i = 0; i < Cii; i++) {
        w1 += phiw[i * Cc + t] * thb[i];
        v1 += thw[i * Cc + t] * phib[i];
    }
    g_w1[t] = w1;
    g_v1[t] = v1;
    float u2 = 0.f;
    for (int k = 0; k < Cii; k++) u2 += Ww[t * Cii + k] * gb[k];
    g_u2[t] = u2;
    if (t < 32) {
        float s = 0.f;
        for (int i = t; i < Cii; i += 32) s += phib[i] * thb[i];
        #pragma unroll
        for (int o = 16; o > 0; o >>= 1) s += __shfl_down_sync(0xffffffffu, s, o);
        if (t == 0) g_sc1[0] = s;
    }
}

// ---------------- shared inner product micro-kernel (R4) -----------------------
__device__ __forceinline__ void mm_compute(const float* __restrict__ Asm,
                                           const float* __restrict__ Bsn,
                                           int warp, int lane, u64 acc[8][2]) {
    #pragma unroll 8
    for (int k = 0; k < 32; k++) {
        ulonglong2 bv = *(const ulonglong2*)&Bsn[k * BPAD + lane * 4];
        float4 a0 = *(const float4*)&Asm[k * APAD + warp * 8];
        float4 a1 = *(const float4*)&Asm[k * APAD + warp * 8 + 4];
        u64 ad;
        ad = pack2(a0.x, a0.x); acc[0][0] = fma2(ad, bv.x, acc[0][0]); acc[0][1] = fma2(ad, bv.y, acc[0][1]);
        ad = pack2(a0.y, a0.y); acc[1][0] = fma2(ad, bv.x, acc[1][0]); acc[1][1] = fma2(ad, bv.y, acc[1][1]);
        ad = pack2(a0.z, a0.z); acc[2][0] = fma2(ad, bv.x, acc[2][0]); acc[2][1] = fma2(ad, bv.y, acc[2][1]);
        ad = pack2(a0.w, a0.w); acc[3][0] = fma2(ad, bv.x, acc[3][0]); acc[3][1] = fma2(ad, bv.y, acc[3][1]);
        ad = pack2(a1.x, a1.x); acc[4][0] = fma2(ad, bv.x, acc[4][0]); acc[4][1] = fma2(ad, bv.y, acc[4][1]);
        ad = pack2(a1.y, a1.y); acc[5][0] = fma2(ad, bv.x, acc[5][0]); acc[5][1] = fma2(ad, bv.y, acc[5][1]);
        ad = pack2(a1.z, a1.z); acc[6][0] = fma2(ad, bv.x, acc[6][0]); acc[6][1] = fma2(ad, bv.y, acc[6][1]);
        ad = pack2(a1.w, a1.w); acc[7][0] = fma2(ad, bv.x, acc[7][0]); acc[7][1] = fma2(ad, bv.y, acc[7][1]);
    }
}

// ---------------- split-K SYRK (R4 exact: 8 tiles, atomic reduce, row sums) ----
__global__ __launch_bounds__(256) void k_syrk(const float* __restrict__ bimg) {
    extern __shared__ __align__(16) float sm[];
    float* Asm = sm;
    float* Bsn = sm + 2 * ABUF;
    int ti = blockIdx.x * 64;
    int tj = blockIdx.y * 128;
    int bz = blockIdx.z >> 4;
    int ks = blockIdx.z & (KSsplit - 1);
    const float* Bb = bimg + (size_t)bz * Cc * Nn;
    int tid = threadIdx.x;
    int lane = tid & 31, warp = tid >> 5;
    int k0 = ks * KPB;

    float4 va[2], vb[4];
    u64 acc[8][2] = {};
    float rs0 = 0.f, rs1 = 0.f;

    int ar[2], ak[2], br[4], bk[4];
    #pragma unroll
    for (int l = 0; l < 2; l++) { int e = tid + l * 256; ar[l] = e >> 3; ak[l] = (e & 7) * 4; }
    #pragma unroll
    for (int l = 0; l < 4; l++) { int e = tid + l * 256; br[l] = e >> 3; bk[l] = (e & 7) * 4; }

    #define SY_LOAD(t) do { \
        int kb = k0 + (t) * 32; \
        _Pragma("unroll") for (int l = 0; l < 2; l++) \
            va[l] = *(const float4*)&Bb[(size_t)(ti + ar[l]) * Nn + kb + ak[l]]; \
        _Pragma("unroll") for (int l = 0; l < 4; l++) \
            vb[l] = *(const float4*)&Bb[(size_t)(tj + br[l]) * Nn + kb + bk[l]]; \
    } while (0)

    #define SY_STORE(buf) do { \
        _Pragma("unroll") for (int l = 0; l < 2; l++) { \
            float tv[4]; *(float4*)tv = va[l]; \
            _Pragma("unroll") for (int q = 0; q < 4; q++) \
                Asm[(buf) * ABUF + (ak[l] + q) * APAD + ar[l]] = tv[q]; \
        } \
        rs0 += va[0].x + va[0].y + va[0].z + va[0].w; \
        rs1 += va[1].x + va[1].y + va[1].z + va[1].w; \
        _Pragma("unroll") for (int l = 0; l < 4; l++) { \
            float tv[4]; *(float4*)tv = vb[l]; \
            _Pragma("unroll") for (int q = 0; q < 4; q++) \
                Bsn[(buf) * BBUF + (bk[l] + q) * BPAD + br[l]] = tv[q]; \
        } \
    } while (0)

    const int T = KPB / 32;   // 8
    SY_LOAD(0);
    SY_STORE(0);
    SY_LOAD(1);
    __syncthreads();
    #pragma unroll 1
    for (int t = 0; t < T; t++) {
        mm_compute(&Asm[(t & 1) * ABUF], &Bsn[(t & 1) * BBUF], warp, lane, acc);
        if (t + 1 < T) SY_STORE((t + 1) & 1);
        __syncthreads();
        if (t + 2 < T) SY_LOAD(t + 2);
    }
    #undef SY_LOAD
    #undef SY_STORE

    if (blockIdx.y == 0) {
        atomicAdd(&g_s[bz * Cc + ti + ar[0]], rs0);
        atomicAdd(&g_s[bz * Cc + ti + ar[1]], rs1);
    }

    float* Rb = g_R + (size_t)bz * Cc * Cc;
    #pragma unroll
    for (int i = 0; i < 8; i++) {
        int ci = ti + warp * 8 + i;
        float2 p0 = unpack2(acc[i][0]), p1 = unpack2(acc[i][1]);
        float* dst = &Rb[(size_t)ci * Cc + tj + lane * 4];
        atomicAdd(dst + 0, p0.x);
        atomicAdd(dst + 1, p0.y);
        atomicAdd(dst + 2, p1.x);
        atomicAdd(dst + 3, p1.y);
    }
}

// ---------------- per-batch vectors: u1, v2, sc2 -------------------------------
__global__ __launch_bounds__(256) void k_vecs(
    const float* __restrict__ gw, const float* __restrict__ phiw,
    const float* __restrict__ phib, const float* __restrict__ Ww,
    const float* __restrict__ thw, const float* __restrict__ thb)
{
    int b = blockIdx.x, t = threadIdx.x;
    __shared__ float ssh[Cc], gs_sm[Cii], ps2_sm[Cii];
    ssh[t] = g_s[b * Cc + t];
    __syncthreads();
    if (t < Cii) {
        float acc = 0.f;
        for (int c = 0; c < Cc; c++) acc += gw[t * Cc + c] * ssh[c];
        gs_sm[t] = acc;
    } else {
        int i = t - Cii;
        float acc = 0.f;
        for (int c = 0; c < Cc; c++) acc += phiw[i * Cc + c] * ssh[c];
        ps2_sm[i] = acc + (float)Nn * phib[i];
    }
    __syncthreads();
    float u1 = 0.f;
    for (int k = 0; k < Cii; k++) u1 += Ww[t * Cii + k] * gs_sm[k];
    g_u1[b * Cc + t] = u1;
    float v2 = 0.f;
    for (int i = 0; i < Cii; i++) v2 += thw[i * Cc + t] * ps2_sm[i];
    g_v2[b * Cc + t] = v2;
    if (t < 32) {
        float s2 = 0.f;
        for (int i = t; i < Cii; i += 32) s2 += ps2_sm[i] * thb[i];
        #pragma unroll
        for (int o = 16; o > 0; o >>= 1) s2 += __shfl_down_sync(0xffffffffu, s2, o);
        if (t == 0) g_sc2[b] = s2;
    }
}

// ---------------- dp from V: dv = (V.w1 + u1 sc1 + u2 sc2)/N --------------------
__global__ __launch_bounds__(256) void k_dvec2(
    const float* __restrict__ gamma, const float* __restrict__ beta,
    const float* __restrict__ mean, const float* __restrict__ var)
{
    int b = blockIdx.x, t = threadIdx.x;
    __shared__ float w1s[Cc];
    w1s[t] = g_w1[t];
    __syncthreads();
    const float* Vrow = g_V + (size_t)b * Cc * Cc + (size_t)t * Cc;
    float dv = 0.f;
    for (int c = 0; c < Cc; c++) dv += Vrow[c] * w1s[c];
    dv = (dv + g_u1[b * Cc + t] * g_sc1[0] + g_u2[t] * g_sc2[b]) * (1.f / (float)Nn);
    float al = gamma[t] * rsqrtf(var[t] + 1e-5f);
    g_dp[b * Cc + t] = al * (dv - mean[t]) + beta[t];
    if (b == 0) g_alpha[t] = al;
}

// ---------------- 64x64-tile batched GEMM (chain, proven R7/R8) -----------------
#define CPAD 68
#define CBUF (32 * CPAD)
__global__ __launch_bounds__(256) void k_mm64(
    const float* __restrict__ A, long long sA, int AT, int lda,
    const float* __restrict__ B, long long sB, int ldb,
    float* __restrict__ C, long long sC, int N, int K, float scale,
    const float* __restrict__ r1a, long long s1a,
    const float* __restrict__ r1b,
    const float* __restrict__ r2a,
    const float* __restrict__ r2b, long long s2b)
{
    __shared__ __align__(16) float As[2 * CBUF], Bs[2 * CBUF];
    int m0 = blockIdx.x * 64, n0 = blockIdx.y * 64, bz = blockIdx.z;
    A += (size_t)bz * sA; B += (size_t)bz * sB; C += (size_t)bz * sC;
    int tid = threadIdx.x;
    int lane = tid & 31, warp = tid >> 5;
    int rbase = warp * 8 + (lane >> 4) * 4;
    int cbase = (lane & 15) * 4;
    int ar = tid & 63, akg = tid >> 6;
    u64 acc[4][2] = {};
    float4 va[2], vb[2];

    #define CM_LOAD(t) do { \
        int kb = (t) * 32; \
        if (!AT) { \
            _Pragma("unroll") for (int l = 0; l < 2; l++) \
                va[l] = *(const float4*)&A[(size_t)(m0 + ar) * lda + kb + akg * 4 + l * 16]; \
        } else { \
            _Pragma("unroll") for (int l = 0; l < 2; l++) { \
                int e = tid + l * 256; \
                va[l] = *(const float4*)&A[(size_t)(kb + (e >> 4)) * lda + m0 + (e & 15) * 4]; \
            } \
        } \
        _Pragma("unroll") for (int l = 0; l < 2; l++) { \
            int e = tid + l * 256; \
            vb[l] = *(const float4*)&B[(size_t)(kb + (e >> 4)) * ldb + n0 + (e & 15) * 4]; \
        } \
    } while (0)

    #define CM_STORE(buf) do { \
        if (!AT) { \
            _Pragma("unroll") for (int l = 0; l < 2; l++) { \
                float tv[4]; *(float4*)tv = va[l]; \
                _Pragma("unroll") for (int q = 0; q < 4; q++) \
                    As[(buf) * CBUF + (akg * 4 + l * 16 + q) * CPAD + ar] = tv[q]; \
            } \
        } else { \
            _Pragma("unroll") for (int l = 0; l < 2; l++) { \
                int e = tid + l * 256; \
                *(float4*)&As[(buf) * CBUF + (e >> 4) * CPAD + (e & 15) * 4] = va[l]; \
            } \
        } \
        _Pragma("unroll") for (int l = 0; l < 2; l++) { \
            int e = tid + l * 256; \
            *(float4*)&Bs[(buf) * CBUF + (e >> 4) * CPAD + (e & 15) * 4] = vb[l]; \
        } \
    } while (0)

    const int T = K / 32;
    CM_LOAD(0);
    CM_STORE(0);
    if (T > 1) CM_LOAD(1);
    __syncthreads();
    #pragma unroll 1
    for (int t = 0; t < T; t++) {
        const float* Ab = &As[(t & 1) * CBUF];
        const float* Bb2 = &Bs[(t & 1) * CBUF];
        #pragma unroll 8
        for (int k = 0; k < 32; k++) {
            float4 a = *(const float4*)&Ab[k * CPAD + rbase];
            ulonglong2 bv = *(const ulonglong2*)&Bb2[k * CPAD + cbase];
            float av[4] = {a.x, a.y, a.z, a.w};
            #pragma unroll
            for (int i = 0; i < 4; i++) {
                u64 ad = pack2(av[i], av[i]);
                acc[i][0] = fma2(ad, bv.x, acc[i][0]);
                acc[i][1] = fma2(ad, bv.y, acc[i][1]);
            }
        }
        if (t + 1 < T) CM_STORE((t + 1) & 1);
        __syncthreads();
        if (t + 2 < T) CM_LOAD(t + 2);
    }
    #undef CM_LOAD
    #undef CM_STORE

    float4 w1v = make_float4(0.f, 0.f, 0.f, 0.f), w2v = w1v;
    if (r1a) {
        w1v = *(const float4*)&r1b[n0 + cbase];
        w2v = *(const float4*)&r2b[(size_t)bz * s2b + n0 + cbase];
    }
    #pragma unroll
    for (int i = 0; i < 4; i++) {
        int m = m0 + rbase + i;
        float2 p0 = unpack2(acc[i][0]), p1 = unpack2(acc[i][1]);
        float4 v = make_float4(p0.x, p0.y, p1.x, p1.y);
        if (r1a) {
            float a1 = r1a[(size_t)bz * s1a + m];
            float a2 = r2a[m];
            v.x += a1 * w1v.x + a2 * w2v.x;
            v.y += a1 * w1v.y + a2 * w2v.y;
            v.z += a1 * w1v.z + a2 * w2v.z;
            v.w += a1 * w1v.w + a2 * w2v.w;
        }
        v.x *= scale; v.y *= scale; v.z *= scale; v.w *= scale;
        *(float4*)&C[(size_t)m * N + n0 + cbase] = v;
    }
}

// ---------------- final: out[b] = alpha .* (Q[b] @ A[b]) + dp  (R4 exact) -------
__global__ __launch_bounds__(256) void k_out(const float* __restrict__ aimg,
                                             float* __restrict__ out)
{
    extern __shared__ __align__(16) float sm[];
    float* Qs  = sm;
    float* Asn = sm + 2 * ABUF;
    int tc = blockIdx.x * 64;
    int tn = blockIdx.y * 128;
    int bz = blockIdx.z;
    const float* Ab = aimg + (size_t)bz * Cc * Nn;
    const float* Qb = g_Q + (size_t)bz * Cc * Cc;
    int tid = threadIdx.x;
    int lane = tid & 31, warp = tid >> 5;

    float4 vq[2], va[4];
    u64 acc[8][2] = {};

    int qr[2], qk[2], akr[4], anq[4];
    #pragma unroll
    for (int l = 0; l < 2; l++) { int e = tid + l * 256; qr[l] = e >> 3; qk[l] = (e & 7) * 4; }
    #pragma unroll
    for (int l = 0; l < 4; l++) { int e = tid + l * 256; akr[l] = e >> 5; anq[l] = (e & 31) * 4; }

    #define FO_LOAD(t) do { \
        int kb = (t) * 32; \
        _Pragma("unroll") for (int l = 0; l < 2; l++) \
            vq[l] = *(const float4*)&Qb[(size_t)(tc + qr[l]) * Cc + kb + qk[l]]; \
        _Pragma("unroll") for (int l = 0; l < 4; l++) \
            va[l] = *(const float4*)&Ab[(size_t)(kb + akr[l]) * Nn + tn + anq[l]]; \
    } while (0)

    #define FO_STORE(buf) do { \
        _Pragma("unroll") for (int l = 0; l < 2; l++) { \
            float tv[4]; *(float4*)tv = vq[l]; \
            _Pragma("unroll") for (int q = 0; q < 4; q++) \
                Qs[(buf) * ABUF + (qk[l] + q) * APAD + qr[l]] = tv[q]; \
        } \
        _Pragma("unroll") for (int l = 0; l < 4; l++) \
            *(float4*)&Asn[(buf) * BBUF + akr[l] * BPAD + anq[l]] = va[l]; \
    } while (0)

    const int T = Cc / 32;   // 8
    FO_LOAD(0);
    FO_STORE(0);
    FO_LOAD(1);
    __syncthreads();
    #pragma unroll 1
    for (int t = 0; t < T; t++) {
        mm_compute(&Qs[(t & 1) * ABUF], &Asn[(t & 1) * BBUF], warp, lane, acc);
        if (t + 1 < T) FO_STORE((t + 1) & 1);
        __syncthreads();
        if (t + 2 < T) FO_LOAD(t + 2);
    }
    #undef FO_LOAD
    #undef FO_STORE

    float* outb = out + (size_t)bz * Cc * Nn;
    #pragma unroll
    for (int i = 0; i < 8; i++) {
        int c = tc + warp * 8 + i;
        float al = g_alpha[c];
        float dpv = g_dp[bz * Cc + c];
        float2 p0 = unpack2(acc[i][0]), p1 = unpack2(acc[i][1]);
        *(float4*)&outb[(size_t)c * Nn + tn + lane * 4] =
            make_float4(al * p0.x + dpv, al * p0.y + dpv, al * p1.x + dpv, al * p1.y + dpv);
    }
}

// -------------------------------------------------------------------------------
static cudaStream_t g_side = nullptr;
static cudaEvent_t g_evFork = nullptr, g_evJoin = nullptr;

extern "C" void kernel_launch(void* const* d_in, const int* in_sizes, int n_in,
                              void* d_out, int out_size) {
    (void)in_sizes; (void)n_in; (void)out_size;
    const float* a       = (const float*)d_in[0];
    const float* bimg    = (const float*)d_in[1];
    const float* theta_w = (const float*)d_in[2];
    const float* theta_b = (const float*)d_in[3];
    const float* phi_w   = (const float*)d_in[4];
    const float* phi_b   = (const float*)d_in[5];
    const float* g_wp    = (const float*)d_in[6];
    const float* g_bp    = (const float*)d_in[7];
    const float* W_wp    = (const float*)d_in[8];
    const float* gamma   = (const float*)d_in[9];
    const float* beta    = (const float*)d_in[10];
    const float* mean    = (const float*)d_in[11];
    const float* var     = (const float*)d_in[12];

    if (!g_side) {   // first call is the (non-captured) correctness run
        cudaFuncSetAttribute(k_syrk, cudaFuncAttributeMaxDynamicSharedMemorySize, SMEM_BYTES);
        cudaFuncSetAttribute(k_out,  cudaFuncAttributeMaxDynamicSharedMemorySize, SMEM_BYTES);
        cudaStreamCreateWithFlags(&g_side, cudaStreamNonBlocking);
        cudaEventCreateWithFlags(&g_evFork, cudaEventDisableTiming);
        cudaEventCreateWithFlags(&g_evJoin, cudaEventDisableTiming);
    }

    float *pR, *pP, *pE, *pV, *pQ, *pU1, *pV1, *pU2, *pV2;
    cudaGetSymbolAddress((void**)&pR,  g_R);
    cudaGetSymbolAddress((void**)&pP,  g_P);
    cudaGetSymbolAddress((void**)&pE,  g_E);
    cudaGetSymbolAddress((void**)&pV,  g_V);
    cudaGetSymbolAddress((void**)&pQ,  g_Q);
    cudaGetSymbolAddress((void**)&pU1, g_u1);
    cudaGetSymbolAddress((void**)&pV1, g_v1);
    cudaGetSymbolAddress((void**)&pU2, g_u2);
    cudaGetSymbolAddress((void**)&pV2, g_v2);

    // ---- fork: weight-only precompute on side stream, hidden under syrk ----
    cudaEventRecord(g_evFork, 0);
    cudaStreamWaitEvent(g_side, g_evFork, 0);
    k_pvec<<<1, 256, 0, g_side>>>(phi_w, theta_w, W_wp, phi_b, theta_b, g_bp);
    // P = W_w @ g_w   [256,256], K=128
    k_mm64<<<dim3(4, 4, 1), 256, 0, g_side>>>(
        W_wp, 0, 0, Cii, g_wp, 0, Cc, pP, 0, Cc, Cii, 1.f,
        nullptr, 0, nullptr, nullptr, nullptr, 0);
    // E = phi_w^T @ theta_w   [256,256], K=128
    k_mm64<<<dim3(4, 4, 1), 256, 0, g_side>>>(
        phi_w, 0, 1, Cc, theta_w, 0, Cc, pE, 0, Cc, Cii, 1.f,
        nullptr, 0, nullptr, nullptr, nullptr, 0);
    cudaEventRecord(g_evJoin, g_side);

    // ---- main stream: data-dependent pipeline ----
    k_zero<<<(Bz * Cc * Cc / 4) / 256, 256>>>();
    k_syrk<<<dim3(4, 2, Bz * KSsplit), 256, SMEM_BYTES>>>(bimg);
    k_vecs<<<Bz, 256>>>(g_wp, phi_w, phi_b, W_wp, theta_w, theta_b);

    cudaStreamWaitEvent(0, g_evJoin, 0);   // join before consuming P/E/pvec

    // V[b] = P @ R[b]   K=256
    k_mm64<<<dim3(4, 4, Bz), 256>>>(pP, 0, 0, Cc, pR, (long long)Cc * Cc, Cc,
                                    pV, (long long)Cc * Cc, Cc, Cc, 1.f,
                                    nullptr, 0, nullptr, nullptr, nullptr, 0);
    // Q[b] = (V[b] @ E + u1 v1^T + u2 v2^T) / N
    k_mm64<<<dim3(4, 4, Bz), 256>>>(pV, (long long)Cc * Cc, 0, Cc, pE, 0, Cc,
                                    pQ, (long long)Cc * Cc, Cc, Cc, 1.f / (float)Nn,
                                    pU1, Cc, pV1, pU2, pV2, Cc);
    // dp from V, u1, u2, scalars
    k_dvec2<<<Bz, 256>>>(gamma, beta, mean, var);

    k_out<<<dim3(4, 32, Bz), 256, SMEM_BYTES>>>(a, (float*)d_out);
}

// round 10
// speedup vs baseline: 1.5820x; 1.1560x over previous
#include <cuda_runtime.h>

#define Bz 4
#define Cc 256
#define Cii 128
#define Nn 4096
#define KSsplit 16
#define KPB (Nn / KSsplit)   // 256 K per split block

typedef unsigned long long u64;

__device__ __forceinline__ u64 pack2(float lo, float hi) {
    u64 r; asm("mov.b64 %0, {%1,%2};" : "=l"(r) : "f"(lo), "f"(hi)); return r;
}
__device__ __forceinline__ float2 unpack2(u64 v) {
    float2 f; asm("mov.b64 {%0,%1}, %2;" : "=f"(f.x), "=f"(f.y) : "l"(v)); return f;
}
__device__ __forceinline__ u64 fma2(u64 a, u64 b, u64 c) {
    u64 d; asm("fma.rn.f32x2 %0, %1, %2, %3;" : "=l"(d) : "l"(a), "l"(b), "l"(c)); return d;
}

// smem swizzle: element (k,c) stored at column c ^ SWZ(k); XOR bits >=2 keep
// float4 groups intact, and (k>>2) varying over 0..7 spreads the column-store
// banks over all 32 banks (proof in notes).
#define SWZ(k) ((((k) >> 2) & 7) << 2)

// ---------------- scratch (static device globals; no allocation) -------------
__device__ float g_R[Bz * Cc * Cc];                 // R = B B^T  per batch (atomics)
__device__ float g_s[Bz * Cc];                      // row sums of b image (atomics)
__device__ float g_gs[Bz * Cii];                    // g_w @ s
__device__ float g_ps2[Bz * Cii];                   // phi_w @ s + N*phi_b
__device__ float g_U[Bz * Cii * Cc];                // g_w @ R
__device__ float g_S[Bz * Cii * Cii];               // G Phi^T
__device__ float g_T[Bz * Cc * Cii];                // W_w @ S / N
__device__ float g_Q[Bz * Cc * Cc];                 // T @ theta_w
__device__ float g_dp[Bz * Cc];                     // folded bias (BN included)
__device__ float g_alpha[Cc];                       // BN scale

// smem tile geometry (transposed k-major tiles)
#define APAD 68
#define BPAD 132
#define ABUF (32 * APAD)
#define BBUF (32 * BPAD)
#define SMEM_BYTES ((2 * ABUF + 2 * BBUF) * 4)   // 51200

// ---------------- zero the atomic-reduce targets ------------------------------
__global__ __launch_bounds__(256) void k_zero() {
    int i = blockIdx.x * 256 + threadIdx.x;
    ((float4*)g_R)[i] = make_float4(0.f, 0.f, 0.f, 0.f);
    if (i < (Bz * Cc) / 4) ((float4*)g_s)[i] = make_float4(0.f, 0.f, 0.f, 0.f);
}

// ---------------- gs = g_w @ s ; ps2 = phi_w @ s + N*phi_b -------------------
__global__ __launch_bounds__(256) void k_gsps(const float* __restrict__ gw,
                                              const float* __restrict__ phiw,
                                              const float* __restrict__ phib) {
    int b = blockIdx.x;
    int tid = threadIdx.x;
    __shared__ float ssh[Cc];
    ssh[tid] = g_s[b * Cc + tid];
    __syncthreads();
    if (tid < Cii) {
        float acc = 0.f;
        for (int c = 0; c < Cc; c++) acc += gw[tid * Cc + c] * ssh[c];
        g_gs[b * Cii + tid] = acc;
    } else {
        int i = tid - Cii;
        float acc = 0.f;
        for (int c = 0; c < Cc; c++) acc += phiw[i * Cc + c] * ssh[c];
        g_ps2[b * Cii + i] = acc + (float)Nn * phib[i];
    }
}

// ---------------- micro kernel: both tiles swizzled (syrk) --------------------
__device__ __forceinline__ void mm_swz_ab(const float* __restrict__ Asm,
                                          const float* __restrict__ Bsn,
                                          int warp, int lane, u64 acc[8][2]) {
    #pragma unroll 8
    for (int k = 0; k < 32; k++) {
        int sw = SWZ(k);
        ulonglong2 bv = *(const ulonglong2*)&Bsn[k * BPAD + ((lane * 4) ^ sw)];
        float4 a0 = *(const float4*)&Asm[k * APAD + ((warp * 8) ^ sw)];
        float4 a1 = *(const float4*)&Asm[k * APAD + ((warp * 8 + 4) ^ sw)];
        u64 ad;
        ad = pack2(a0.x, a0.x); acc[0][0] = fma2(ad, bv.x, acc[0][0]); acc[0][1] = fma2(ad, bv.y, acc[0][1]);
        ad = pack2(a0.y, a0.y); acc[1][0] = fma2(ad, bv.x, acc[1][0]); acc[1][1] = fma2(ad, bv.y, acc[1][1]);
        ad = pack2(a0.z, a0.z); acc[2][0] = fma2(ad, bv.x, acc[2][0]); acc[2][1] = fma2(ad, bv.y, acc[2][1]);
        ad = pack2(a0.w, a0.w); acc[3][0] = fma2(ad, bv.x, acc[3][0]); acc[3][1] = fma2(ad, bv.y, acc[3][1]);
        ad = pack2(a1.x, a1.x); acc[4][0] = fma2(ad, bv.x, acc[4][0]); acc[4][1] = fma2(ad, bv.y, acc[4][1]);
        ad = pack2(a1.y, a1.y); acc[5][0] = fma2(ad, bv.x, acc[5][0]); acc[5][1] = fma2(ad, bv.y, acc[5][1]);
        ad = pack2(a1.z, a1.z); acc[6][0] = fma2(ad, bv.x, acc[6][0]); acc[6][1] = fma2(ad, bv.y, acc[6][1]);
        ad = pack2(a1.w, a1.w); acc[7][0] = fma2(ad, bv.x, acc[7][0]); acc[7][1] = fma2(ad, bv.y, acc[7][1]);
    }
}

// ---------------- micro kernel: only A tile swizzled (k_out) ------------------
__device__ __forceinline__ void mm_swz_a(const float* __restrict__ Asm,
                                         const float* __restrict__ Bsn,
                                         int warp, int lane, u64 acc[8][2]) {
    #pragma unroll 8
    for (int k = 0; k < 32; k++) {
        int sw = SWZ(k);
        ulonglong2 bv = *(const ulonglong2*)&Bsn[k * BPAD + lane * 4];
        float4 a0 = *(const float4*)&Asm[k * APAD + ((warp * 8) ^ sw)];
        float4 a1 = *(const float4*)&Asm[k * APAD + ((warp * 8 + 4) ^ sw)];
        u64 ad;
        ad = pack2(a0.x, a0.x); acc[0][0] = fma2(ad, bv.x, acc[0][0]); acc[0][1] = fma2(ad, bv.y, acc[0][1]);
        ad = pack2(a0.y, a0.y); acc[1][0] = fma2(ad, bv.x, acc[1][0]); acc[1][1] = fma2(ad, bv.y, acc[1][1]);
        ad = pack2(a0.z, a0.z); acc[2][0] = fma2(ad, bv.x, acc[2][0]); acc[2][1] = fma2(ad, bv.y, acc[2][1]);
        ad = pack2(a0.w, a0.w); acc[3][0] = fma2(ad, bv.x, acc[3][0]); acc[3][1] = fma2(ad, bv.y, acc[3][1]);
        ad = pack2(a1.x, a1.x); acc[4][0] = fma2(ad, bv.x, acc[4][0]); acc[4][1] = fma2(ad, bv.y, acc[4][1]);
        ad = pack2(a1.y, a1.y); acc[5][0] = fma2(ad, bv.x, acc[5][0]); acc[5][1] = fma2(ad, bv.y, acc[5][1]);
        ad = pack2(a1.z, a1.z); acc[6][0] = fma2(ad, bv.x, acc[6][0]); acc[6][1] = fma2(ad, bv.y, acc[6][1]);
        ad = pack2(a1.w, a1.w); acc[7][0] = fma2(ad, bv.x, acc[7][0]); acc[7][1] = fma2(ad, bv.y, acc[7][1]);
    }
}

// ---------------- split-K SYRK (R4 + swizzled stores) --------------------------
__global__ __launch_bounds__(256) void k_syrk(const float* __restrict__ bimg) {
    extern __shared__ __align__(16) float sm[];
    float* Asm = sm;
    float* Bsn = sm + 2 * ABUF;
    int ti = blockIdx.x * 64;
    int tj = blockIdx.y * 128;
    int bz = blockIdx.z >> 4;
    int ks = blockIdx.z & (KSsplit - 1);
    const float* Bb = bimg + (size_t)bz * Cc * Nn;
    int tid = threadIdx.x;
    int lane = tid & 31, warp = tid >> 5;
    int k0 = ks * KPB;

    float4 va[2], vb[4];
    u64 acc[8][2] = {};
    float rs0 = 0.f, rs1 = 0.f;

    int ar[2], ak[2], br[4], bk[4];
    #pragma unroll
    for (int l = 0; l < 2; l++) { int e = tid + l * 256; ar[l] = e >> 3; ak[l] = (e & 7) * 4; }
    #pragma unroll
    for (int l = 0; l < 4; l++) { int e = tid + l * 256; br[l] = e >> 3; bk[l] = (e & 7) * 4; }

    #define SY_LOAD(t) do { \
        int kb = k0 + (t) * 32; \
        _Pragma("unroll") for (int l = 0; l < 2; l++) \
            va[l] = *(const float4*)&Bb[(size_t)(ti + ar[l]) * Nn + kb + ak[l]]; \
        _Pragma("unroll") for (int l = 0; l < 4; l++) \
            vb[l] = *(const float4*)&Bb[(size_t)(tj + br[l]) * Nn + kb + bk[l]]; \
    } while (0)

    #define SY_STORE(buf) do { \
        _Pragma("unroll") for (int l = 0; l < 2; l++) { \
            float tv[4]; *(float4*)tv = va[l]; \
            int cs = ar[l] ^ SWZ(ak[l]); \
            _Pragma("unroll") for (int q = 0; q < 4; q++) \
                Asm[(buf) * ABUF + (ak[l] + q) * APAD + cs] = tv[q]; \
        } \
        rs0 += va[0].x + va[0].y + va[0].z + va[0].w; \
        rs1 += va[1].x + va[1].y + va[1].z + va[1].w; \
        _Pragma("unroll") for (int l = 0; l < 4; l++) { \
            float tv[4]; *(float4*)tv = vb[l]; \
            int cs = br[l] ^ SWZ(bk[l]); \
            _Pragma("unroll") for (int q = 0; q < 4; q++) \
                Bsn[(buf) * BBUF + (bk[l] + q) * BPAD + cs] = tv[q]; \
        } \
    } while (0)

    const int T = KPB / 32;   // 8
    SY_LOAD(0);
    SY_STORE(0);
    SY_LOAD(1);
    __syncthreads();
    #pragma unroll 1
    for (int t = 0; t < T; t++) {
        mm_swz_ab(&Asm[(t & 1) * ABUF], &Bsn[(t & 1) * BBUF], warp, lane, acc);
        if (t + 1 < T) SY_STORE((t + 1) & 1);
        __syncthreads();
        if (t + 2 < T) SY_LOAD(t + 2);
    }
    #undef SY_LOAD
    #undef SY_STORE

    if (blockIdx.y == 0) {
        atomicAdd(&g_s[bz * Cc + ti + ar[0]], rs0);
        atomicAdd(&g_s[bz * Cc + ti + ar[1]], rs1);
    }

    float* Rb = g_R + (size_t)bz * Cc * Cc;
    #pragma unroll
    for (int i = 0; i < 8; i++) {
        int ci = ti + warp * 8 + i;
        float2 p0 = unpack2(acc[i][0]), p1 = unpack2(acc[i][1]);
        float* dst = &Rb[(size_t)ci * Cc + tj + lane * 4];
        atomicAdd(dst + 0, p0.x);
        atomicAdd(dst + 1, p0.y);
        atomicAdd(dst + 2, p1.x);
        atomicAdd(dst + 3, p1.y);
    }
}

// ---------------- generic small batched GEMM (32x32 tiles, R4) -----------------
__global__ __launch_bounds__(256) void k_gemm32(
    const float* __restrict__ A, long long sA,
    const float* __restrict__ B, long long sB,
    float* __restrict__ C, long long sC,
    int M, int N, int K, int BT, float scale,
    const float* __restrict__ r1a, long long s1a,
    const float* __restrict__ r1b, long long s1b,
    const float* __restrict__ r2a, long long s2a,
    const float* __restrict__ r2b, long long s2b)
{
    int m0 = blockIdx.x * 32, n0 = blockIdx.y * 32, bz = blockIdx.z;
    A += (size_t)bz * sA; B += (size_t)bz * sB; C += (size_t)bz * sC;
    __shared__ float As[32][33], Bs[32][33];
    int tid = threadIdx.x, tx = tid & 15, ty = tid >> 4;
    float acc00 = 0.f, acc01 = 0.f, acc10 = 0.f, acc11 = 0.f;
    for (int k0 = 0; k0 < K; k0 += 32) {
        #pragma unroll
        for (int l = 0; l < 4; l++) {
            int idx = tid + l * 256;
            int r = idx >> 5, k = idx & 31;
            As[k][r] = A[(size_t)(m0 + r) * K + k0 + k];
            if (!BT) Bs[r][k] = B[(size_t)(k0 + r) * N + n0 + k];
            else     Bs[k][r] = B[(size_t)(n0 + r) * K + k0 + k];
        }
        __syncthreads();
        #pragma unroll
        for (int k = 0; k < 32; k++) {
            float a0 = As[k][ty * 2], a1 = As[k][ty * 2 + 1];
            float b0 = Bs[k][tx * 2], b1 = Bs[k][tx * 2 + 1];
            acc00 += a0 * b0; acc01 += a0 * b1;
            acc10 += a1 * b0; acc11 += a1 * b1;
        }
        __syncthreads();
    }
    float e[2][2] = {{acc00, acc01}, {acc10, acc11}};
    #pragma unroll
    for (int ii = 0; ii < 2; ii++)
        #pragma unroll
        for (int jj = 0; jj < 2; jj++) {
            int m = m0 + ty * 2 + ii, n = n0 + tx * 2 + jj;
            float v = e[ii][jj] * scale;
            if (r1a)
                v += r1a[(size_t)bz * s1a + m] * r1b[(size_t)bz * s1b + n]
                   + r2a[(size_t)bz * s2a + m] * r2b[(size_t)bz * s2b + n];
            C[(size_t)m * N + n] = v;
        }
}

// ---------------- fold theta_b + BN into per-(b,c) bias & alpha --------------
__global__ __launch_bounds__(256) void k_dvec(
    const float* __restrict__ theta_b, const float* __restrict__ gamma,
    const float* __restrict__ beta, const float* __restrict__ mean,
    const float* __restrict__ var)
{
    int b = blockIdx.x, c = threadIdx.x;
    const float* Trow = g_T + ((size_t)b * Cc + c) * Cii;
    float d = 0.f;
    for (int i = 0; i < Cii; i++) d += Trow[i] * theta_b[i];
    float al = gamma[c] * rsqrtf(var[c] + 1e-5f);
    g_dp[b * Cc + c] = al * (d - mean[c]) + beta[c];
    if (b == 0) g_alpha[c] = al;
}

// ---------------- final: out[b] = alpha .* (Q[b] @ A[b]) + dp  (R4 + Q swizzle) -
__global__ __launch_bounds__(256) void k_out(const float* __restrict__ aimg,
                                             float* __restrict__ out)
{
    extern __shared__ __align__(16) float sm[];
    float* Qs  = sm;
    float* Asn = sm + 2 * ABUF;
    int tc = blockIdx.x * 64;
    int tn = blockIdx.y * 128;
    int bz = blockIdx.z;
    const float* Ab = aimg + (size_t)bz * Cc * Nn;
    const float* Qb = g_Q + (size_t)bz * Cc * Cc;
    int tid = threadIdx.x;
    int lane = tid & 31, warp = tid >> 5;

    float4 vq[2], va[4];
    u64 acc[8][2] = {};

    int qr[2], qk[2], akr[4], anq[4];
    #pragma unroll
    for (int l = 0; l < 2; l++) { int e = tid + l * 256; qr[l] = e >> 3; qk[l] = (e & 7) * 4; }
    #pragma unroll
    for (int l = 0; l < 4; l++) { int e = tid + l * 256; akr[l] = e >> 5; anq[l] = (e & 31) * 4; }

    #define FO_LOAD(t) do { \
        int kb = (t) * 32; \
        _Pragma("unroll") for (int l = 0; l < 2; l++) \
            vq[l] = *(const float4*)&Qb[(size_t)(tc + qr[l]) * Cc + kb + qk[l]]; \
        _Pragma("unroll") for (int l = 0; l < 4; l++) \
            va[l] = *(const float4*)&Ab[(size_t)(kb + akr[l]) * Nn + tn + anq[l]]; \
    } while (0)

    #define FO_STORE(buf) do { \
        _Pragma("unroll") for (int l = 0; l < 2; l++) { \
            float tv[4]; *(float4*)tv = vq[l]; \
            int cs = qr[l] ^ SWZ(qk[l]); \
            _Pragma("unroll") for (int q = 0; q < 4; q++) \
                Qs[(buf) * ABUF + (qk[l] + q) * APAD + cs] = tv[q]; \
        } \
        _Pragma("unroll") for (int l = 0; l < 4; l++) \
            *(float4*)&Asn[(buf) * BBUF + akr[l] * BPAD + anq[l]] = va[l]; \
    } while (0)

    const int T = Cc / 32;   // 8
    FO_LOAD(0);
    FO_STORE(0);
    FO_LOAD(1);
    __syncthreads();
    #pragma unroll 1
    for (int t = 0; t < T; t++) {
        mm_swz_a(&Qs[(t & 1) * ABUF], &Asn[(t & 1) * BBUF], warp, lane, acc);
        if (t + 1 < T) FO_STORE((t + 1) & 1);
        __syncthreads();
        if (t + 2 < T) FO_LOAD(t + 2);
    }
    #undef FO_LOAD
    #undef FO_STORE

    float* outb = out + (size_t)bz * Cc * Nn;
    #pragma unroll
    for (int i = 0; i < 8; i++) {
        int c = tc + warp * 8 + i;
        float al = g_alpha[c];
        float dpv = g_dp[bz * Cc + c];
        float2 p0 = unpack2(acc[i][0]), p1 = unpack2(acc[i][1]);
        *(float4*)&outb[(size_t)c * Nn + tn + lane * 4] =
            make_float4(al * p0.x + dpv, al * p0.y + dpv, al * p1.x + dpv, al * p1.y + dpv);
    }
}

// -----------------------------------------------------------------------------
extern "C" void kernel_launch(void* const* d_in, const int* in_sizes, int n_in,
                              void* d_out, int out_size) {
    (void)in_sizes; (void)n_in; (void)out_size;
    const float* a       = (const float*)d_in[0];
    const float* bimg    = (const float*)d_in[1];
    const float* theta_w = (const float*)d_in[2];
    const float* theta_b = (const float*)d_in[3];
    const float* phi_w   = (const float*)d_in[4];
    const float* phi_b   = (const float*)d_in[5];
    const float* g_wp    = (const float*)d_in[6];
    const float* g_bp    = (const float*)d_in[7];
    const float* W_wp    = (const float*)d_in[8];
    const float* gamma   = (const float*)d_in[9];
    const float* beta    = (const float*)d_in[10];
    const float* mean    = (const float*)d_in[11];
    const float* var     = (const float*)d_in[12];

    static int attr_done = 0;
    if (!attr_done) {
        cudaFuncSetAttribute(k_syrk, cudaFuncAttributeMaxDynamicSharedMemorySize, SMEM_BYTES);
        cudaFuncSetAttribute(k_out,  cudaFuncAttributeMaxDynamicSharedMemorySize, SMEM_BYTES);
        attr_done = 1;
    }

    float *pR, *pU, *pS, *pT, *pQ, *pGs, *pPs2;
    cudaGetSymbolAddress((void**)&pR,   g_R);
    cudaGetSymbolAddress((void**)&pU,   g_U);
    cudaGetSymbolAddress((void**)&pS,   g_S);
    cudaGetSymbolAddress((void**)&pT,   g_T);
    cudaGetSymbolAddress((void**)&pQ,   g_Q);
    cudaGetSymbolAddress((void**)&pGs,  g_gs);
    cudaGetSymbolAddress((void**)&pPs2, g_ps2);

    k_zero<<<(Bz * Cc * Cc / 4) / 256, 256>>>();
    k_syrk<<<dim3(4, 2, Bz * KSsplit), 256, SMEM_BYTES>>>(bimg);
    k_gsps<<<Bz, 256>>>(g_wp, phi_w, phi_b);

    // U[b] = g_w @ R[b]
    k_gemm32<<<dim3(Cii / 32, Cc / 32, Bz), 256>>>(
        g_wp, 0, pR, (long long)Cc * Cc, pU, (long long)Cii * Cc,
        Cii, Cc, Cc, 0, 1.f,
        nullptr, 0, nullptr, 0, nullptr, 0, nullptr, 0);
    // S[b] = U[b] @ phi_w^T + gs*phib^T + gb*ps2^T
    k_gemm32<<<dim3(Cii / 32, Cii / 32, Bz), 256>>>(
        pU, (long long)Cii * Cc, phi_w, 0, pS, (long long)Cii * Cii,
        Cii, Cii, Cc, 1, 1.f,
        pGs, Cii, phi_b, 0, g_bp, 0, pPs2, Cii);
    // T[b] = W_w @ S[b] / N
    k_gemm32<<<dim3(Cc / 32, Cii / 32, Bz), 256>>>(
        W_wp, 0, pS, (long long)Cii * Cii, pT, (long long)Cc * Cii,
        Cc, Cii, Cii, 0, 1.f / (float)Nn,
        nullptr, 0, nullptr, 0, nullptr, 0, nullptr, 0);
    // Q[b] = T[b] @ theta_w
    k_gemm32<<<dim3(Cc / 32, Cc / 32, Bz), 256>>>(
        pT, (long long)Cc * Cii, theta_w, 0, pQ, (long long)Cc * Cc,
        Cc, Cc, Cii, 0, 1.f,
        nullptr, 0, nullptr, 0, nullptr, 0, nullptr, 0);

    k_dvec<<<Bz, 256>>>(theta_b, gamma, beta, mean, var);
    k_out<<<dim3(4, 32, Bz), 256, SMEM_BYTES>>>(a, (float*)d_out);
}